// round 6
// baseline (speedup 1.0000x reference)
#include <cuda_runtime.h>
#include <cuda_bf16.h>
#include <cstdint>

// q,k,v: (H=8, B=256, L=128, D=64) fp32 ; pos_bias: (H,1,L,L)
// d_out = [ out (H,B,L,D) | attn (H,B,L,L) ]
// 2-CTA cluster per (h,b): CTA c owns keys/values j in [64c, 64c+64).
#define HH 8
#define BSZ 256
#define LL 128
#define DD 64
#define STR 36   // u32 row stride; 36 % 32 == 4 -> ldmatrix conflict-free

// u32-index smem offsets
#define OQH 0                      // Q hi: 128 x 36
#define OQL (OQH + 128 * STR)      // Q lo
#define OKH (OQL + 128 * STR)      // K hi: 64 x 36
#define OKL (OKH + 64 * STR)
#define OVH (OKL + 64 * STR)       // V hi: 64 x 36
#define OVL (OVH + 64 * STR)
#define OMS (OVL + 64 * STR)       // (m,s) exchange: 128 rows x 2 floats
#define OOB OKH                    // partial-O exchange buffer (reuses dead K tiles)
#define SMEM_U32 (OMS + 256)       // 18688 u32 = 74752 B -> 3 CTAs/SM

static __device__ __forceinline__ uint32_t packbf(float lo, float hi) {
    uint32_t r;
    asm("cvt.rn.bf16x2.f32 %0, %1, %2;" : "=r"(r) : "f"(hi), "f"(lo));
    return r;
}
static __device__ __forceinline__ float bf16rt(float x) {
    return __bfloat162float(__float2bfloat16_rn(x));
}
static __device__ __forceinline__ uint32_t smem_u32(const void* p) {
    uint32_t a;
    asm("{ .reg .u64 t; cvta.to.shared.u64 t, %1; cvt.u32.u64 %0, t; }" : "=r"(a) : "l"(p));
    return a;
}
static __device__ __forceinline__ uint32_t mapa_peer(uint32_t addr, uint32_t rank) {
    uint32_t r;
    asm("mapa.shared::cluster.u32 %0, %1, %2;" : "=r"(r) : "r"(addr), "r"(rank));
    return r;
}
#define ST_CL_V2(a, x, y) \
    asm volatile("st.shared::cluster.v2.f32 [%0], {%1,%2};" :: "r"(a), "f"(x), "f"(y) : "memory")
#define CLUSTER_SYNC() do { \
    asm volatile("barrier.cluster.arrive.aligned;" ::: "memory"); \
    asm volatile("barrier.cluster.wait.aligned;" ::: "memory"); } while (0)

static __device__ __forceinline__ void mma16816(float* d, const uint32_t* a,
                                                uint32_t b0, uint32_t b1) {
    asm volatile(
        "mma.sync.aligned.m16n8k16.row.col.f32.bf16.bf16.f32 "
        "{%0,%1,%2,%3}, {%4,%5,%6,%7}, {%8,%9}, {%0,%1,%2,%3};"
        : "+f"(d[0]), "+f"(d[1]), "+f"(d[2]), "+f"(d[3])
        : "r"(a[0]), "r"(a[1]), "r"(a[2]), "r"(a[3]), "r"(b0), "r"(b1));
}
#define LDSM_X4(r, a) \
    asm volatile("ldmatrix.sync.aligned.m8n8.x4.shared.b16 {%0,%1,%2,%3}, [%4];" \
        : "=r"((r)[0]), "=r"((r)[1]), "=r"((r)[2]), "=r"((r)[3]) : "r"(a))
#define LDSM_X4T(r, a) \
    asm volatile("ldmatrix.sync.aligned.m8n8.x4.trans.shared.b16 {%0,%1,%2,%3}, [%4];" \
        : "=r"((r)[0]), "=r"((r)[1]), "=r"((r)[2]), "=r"((r)[3]) : "r"(a))

static __device__ __forceinline__ void split4(float4 x, uint2& h, uint2& l) {
    float hx = bf16rt(x.x), hy = bf16rt(x.y), hz = bf16rt(x.z), hw = bf16rt(x.w);
    h = make_uint2(packbf(hx, hy), packbf(hz, hw));
    l = make_uint2(packbf(x.x - hx, x.y - hy), packbf(x.z - hz, x.w - hw));
}

__global__ __launch_bounds__(256, 3) __cluster_dims__(2, 1, 1)
void attn_cl_kernel(const float* __restrict__ qg_,
                    const float* __restrict__ kg_,
                    const float* __restrict__ vg_,
                    const float* __restrict__ biasg,
                    float* __restrict__ outg,
                    float* __restrict__ attng)
{
    extern __shared__ uint32_t smu[];

    const int t = threadIdx.x;
    const int bx = blockIdx.x;
    const int b = bx >> 1;
    const uint32_t c = bx & 1, p = c ^ 1;   // my j-half / peer rank
    const int h = blockIdx.y;

    const size_t base  = (((size_t)h * BSZ + b) * LL) * DD;
    const size_t abase = (((size_t)h * BSZ + b) * LL) * LL;
    const float4* q4 = (const float4*)(qg_ + base);
    const float4* k4 = (const float4*)(kg_ + base + (size_t)(64 * c) * DD);
    const float4* v4 = (const float4*)(vg_ + base + (size_t)(64 * c) * DD);
    const float*  bg = biasg + (size_t)h * LL * LL + 64 * c;
    float*        ag = attng + abase + 64 * c;
    float*        og = outg + base;

    // ---- Stage Q (full) + K,V (my half) as bf16 hi/lo ----
    #pragma unroll
    for (int it = 0; it < 8; ++it) {
        int idx = t + it * 256;               // 0..2047
        int so = (idx >> 4) * STR + 2 * (idx & 15);
        uint2 hh, ll;
        split4(q4[idx], hh, ll);
        *(uint2*)&smu[OQH + so] = hh; *(uint2*)&smu[OQL + so] = ll;
    }
    #pragma unroll
    for (int it = 0; it < 4; ++it) {
        int idx = t + it * 256;               // 0..1023 (64 rows)
        int so = (idx >> 4) * STR + 2 * (idx & 15);
        uint2 hh, ll;
        split4(k4[idx], hh, ll);
        *(uint2*)&smu[OKH + so] = hh; *(uint2*)&smu[OKL + so] = ll;
        split4(v4[idx], hh, ll);
        *(uint2*)&smu[OVH + so] = hh; *(uint2*)&smu[OVL + so] = ll;
    }
    __syncthreads();

    const int w = t >> 5, lane = t & 31;
    const int g = lane >> 2, tq = lane & 3;
    const int i0 = w * 16;
    const int rA = i0 + g, rB = i0 + g + 8;

    const uint32_t sb = smem_u32(smu);
    const int lr = lane & 7, lsel = lane >> 3;
    const uint32_t aQh = sb + 4u * (OQH + (uint32_t)((i0 + (lsel & 1) * 8 + lr) * STR
                                                     + (lsel >> 1) * 4));
    const uint32_t aQl = aQh + 4u * (OQL - OQH);
    const uint32_t aKb = sb + 4u * ((lsel >= 2 ? OKL : OKH)
                                    + (uint32_t)(lr * STR + (lsel & 1) * 4));
    const uint32_t aVb = sb + 4u * ((lsel >= 2 ? OVL : OVH)
                                    + (uint32_t)(((lsel & 1) * 8 + lr) * STR));

    // =================== MMA 1: S = Q K^T over my 64 keys ===================
    float S[8][4];
    #pragma unroll
    for (int nt = 0; nt < 8; ++nt)
        S[nt][0] = S[nt][1] = S[nt][2] = S[nt][3] = 0.f;

    #pragma unroll
    for (int u = 0; u < 4; ++u) {
        uint32_t qh[4], ql[4];
        LDSM_X4(qh, aQh + 32u * u);
        LDSM_X4(ql, aQl + 32u * u);
        #pragma unroll
        for (int nt = 0; nt < 8; ++nt) {
            uint32_t bb[4];
            LDSM_X4(bb, aKb + (uint32_t)(nt * 8 * STR * 4) + 32u * u);
            mma16816(S[nt], qh, bb[0], bb[1]);
            mma16816(S[nt], qh, bb[2], bb[3]);
            mma16816(S[nt], ql, bb[0], bb[1]);
        }
    }

    // =================== partial softmax on my half ===================
    const float* bA = bg + (size_t)rA * LL;
    const float* bB = bg + (size_t)rB * LL;
    float mA = -1e30f, mB = -1e30f;
    #pragma unroll
    for (int nt = 0; nt < 8; ++nt) {
        float2 b0 = __ldg((const float2*)&bA[8 * nt + 2 * tq]);
        float2 b1 = __ldg((const float2*)&bB[8 * nt + 2 * tq]);
        S[nt][0] = fmaf(S[nt][0], 0.125f, b0.x);
        S[nt][1] = fmaf(S[nt][1], 0.125f, b0.y);
        S[nt][2] = fmaf(S[nt][2], 0.125f, b1.x);
        S[nt][3] = fmaf(S[nt][3], 0.125f, b1.y);
        mA = fmaxf(mA, fmaxf(S[nt][0], S[nt][1]));
        mB = fmaxf(mB, fmaxf(S[nt][2], S[nt][3]));
    }
    mA = fmaxf(mA, __shfl_xor_sync(0xffffffffu, mA, 1));
    mA = fmaxf(mA, __shfl_xor_sync(0xffffffffu, mA, 2));
    mB = fmaxf(mB, __shfl_xor_sync(0xffffffffu, mB, 1));
    mB = fmaxf(mB, __shfl_xor_sync(0xffffffffu, mB, 2));

    float sA = 0.f, sB = 0.f;
    #pragma unroll
    for (int nt = 0; nt < 8; ++nt) {
        S[nt][0] = __expf(S[nt][0] - mA); sA += S[nt][0];
        S[nt][1] = __expf(S[nt][1] - mA); sA += S[nt][1];
        S[nt][2] = __expf(S[nt][2] - mB); sB += S[nt][2];
        S[nt][3] = __expf(S[nt][3] - mB); sB += S[nt][3];
    }
    sA += __shfl_xor_sync(0xffffffffu, sA, 1);
    sA += __shfl_xor_sync(0xffffffffu, sA, 2);
    sB += __shfl_xor_sync(0xffffffffu, sB, 1);
    sB += __shfl_xor_sync(0xffffffffu, sB, 2);

    // ---- exchange (m, s) with peer CTA ----
    if (tq == 0) {
        uint32_t pms = mapa_peer(sb + 4u * OMS, p);
        ST_CL_V2(pms + 8u * rA, mA, sA);
        ST_CL_V2(pms + 8u * rB, mB, sB);
    }
    CLUSTER_SYNC();   // barrier #1: (m,s) exchanged; both CTAs past MMA1

    {
        const float* ms = (const float*)&smu[OMS];
        float2 oA = *(const float2*)&ms[2 * rA];
        float2 oB = *(const float2*)&ms[2 * rB];
        float MA = fmaxf(mA, oA.x);
        float MB = fmaxf(mB, oB.x);
        float eA = __expf(mA - MA), eB = __expf(mB - MB);
        float SA = fmaf(oA.y, __expf(oA.x - MA), sA * eA);
        float SB = fmaf(oB.y, __expf(oB.x - MB), sB * eB);
        float scA = eA / SA, scB = eB / SB;
        float* aA = ag + (size_t)rA * LL;
        float* aB = ag + (size_t)rB * LL;
        #pragma unroll
        for (int nt = 0; nt < 8; ++nt) {
            S[nt][0] *= scA; S[nt][1] *= scA; S[nt][2] *= scB; S[nt][3] *= scB;
            *(float2*)&aA[8 * nt + 2 * tq] = make_float2(S[nt][0], S[nt][1]);
            *(float2*)&aB[8 * nt + 2 * tq] = make_float2(S[nt][2], S[nt][3]);
        }
    }

    // ---- pack P hi/lo fragments (k over my 64 j, 4 chunks) ----
    uint32_t PH[4][4], PL[4][4];
    #pragma unroll
    for (int u = 0; u < 4; ++u) {
        float p0 = S[2 * u][0], p1 = S[2 * u][1], p2 = S[2 * u][2], p3 = S[2 * u][3];
        float h0 = bf16rt(p0), h1 = bf16rt(p1), h2 = bf16rt(p2), h3 = bf16rt(p3);
        PH[u][0] = packbf(h0, h1);           PH[u][1] = packbf(h2, h3);
        PL[u][0] = packbf(p0 - h0, p1 - h1); PL[u][1] = packbf(p2 - h2, p3 - h3);
        p0 = S[2 * u + 1][0]; p1 = S[2 * u + 1][1];
        p2 = S[2 * u + 1][2]; p3 = S[2 * u + 1][3];
        h0 = bf16rt(p0); h1 = bf16rt(p1); h2 = bf16rt(p2); h3 = bf16rt(p3);
        PH[u][2] = packbf(h0, h1);           PH[u][3] = packbf(h2, h3);
        PL[u][2] = packbf(p0 - h0, p1 - h1); PL[u][3] = packbf(p2 - h2, p3 - h3);
    }

    // =================== MMA 2a: partner's d-half, ship via DSMEM ===================
    {
        float O[4][4];
        #pragma unroll
        for (int i = 0; i < 4; ++i) O[i][0] = O[i][1] = O[i][2] = O[i][3] = 0.f;
        #pragma unroll
        for (int u = 0; u < 4; ++u)
            #pragma unroll
            for (int i = 0; i < 4; ++i) {
                uint32_t bb[4];
                LDSM_X4T(bb, aVb + (uint32_t)(u * 16 * STR * 4)
                              + (uint32_t)((4 * p + i) * 16));
                mma16816(O[i], PH[u], bb[0], bb[1]);
                mma16816(O[i], PH[u], bb[2], bb[3]);
                mma16816(O[i], PL[u], bb[0], bb[1]);
            }
        uint32_t pob = mapa_peer(sb + 4u * OOB, p);
        #pragma unroll
        for (int i = 0; i < 4; ++i) {
            ST_CL_V2(pob + 4u * (uint32_t)(rA * STR + 8 * i + 2 * tq), O[i][0], O[i][1]);
            ST_CL_V2(pob + 4u * (uint32_t)(rB * STR + 8 * i + 2 * tq), O[i][2], O[i][3]);
        }
    }

    // =================== MMA 2b: my d-half ===================
    float O[4][4];
    #pragma unroll
    for (int i = 0; i < 4; ++i) O[i][0] = O[i][1] = O[i][2] = O[i][3] = 0.f;
    #pragma unroll
    for (int u = 0; u < 4; ++u)
        #pragma unroll
        for (int i = 0; i < 4; ++i) {
            uint32_t bb[4];
            LDSM_X4T(bb, aVb + (uint32_t)(u * 16 * STR * 4)
                          + (uint32_t)((4 * c + i) * 16));
            mma16816(O[i], PH[u], bb[0], bb[1]);
            mma16816(O[i], PH[u], bb[2], bb[3]);
            mma16816(O[i], PL[u], bb[0], bb[1]);
        }

    CLUSTER_SYNC();   // barrier #2: partner's partial O landed in my OOB

    {
        const float* ob = (const float*)&smu[OOB];
        float* oA = og + (size_t)rA * DD + 32 * c;
        float* oB = og + (size_t)rB * DD + 32 * c;
        #pragma unroll
        for (int i = 0; i < 4; ++i) {
            float2 xa = *(const float2*)&ob[rA * STR + 8 * i + 2 * tq];
            float2 xb = *(const float2*)&ob[rB * STR + 8 * i + 2 * tq];
            *(float2*)&oA[8 * i + 2 * tq] = make_float2(O[i][0] + xa.x, O[i][1] + xa.y);
            *(float2*)&oB[8 * i + 2 * tq] = make_float2(O[i][2] + xb.x, O[i][3] + xb.y);
        }
    }
}

extern "C" void kernel_launch(void* const* d_in, const int* in_sizes, int n_in,
                              void* d_out, int out_size)
{
    const float* q    = (const float*)d_in[0];
    const float* k    = (const float*)d_in[1];
    const float* v    = (const float*)d_in[2];
    const float* bias = (const float*)d_in[3];

    float* out  = (float*)d_out;
    float* attn = out + (size_t)HH * BSZ * LL * DD;

    const size_t smem = (size_t)SMEM_U32 * 4;   // 74752 B
    cudaFuncSetAttribute(attn_cl_kernel,
                         cudaFuncAttributeMaxDynamicSharedMemorySize, (int)smem);

    dim3 grid(2 * BSZ, HH);
    attn_cl_kernel<<<grid, 256, smem>>>(q, k, v, bias, out, attn);
}

// round 7
// speedup vs baseline: 1.3397x; 1.3397x over previous
#include <cuda_runtime.h>
#include <cuda_fp16.h>
#include <cstdint>

// q,k,v: (H=8, B=256, L=128, D=64) fp32 ; pos_bias: (H,1,L,L)
// d_out = [ out (H,B,L,D) | attn (H,B,L,L) ]
// fp16 split precision, 2-pass: S = qh*(kh+kl), O = ph*(vh+vl).
#define HH 8
#define BSZ 256
#define LL 128
#define DD 64
#define STR 36   // u32 stride per tile row; 36 % 32 == 4 -> ldmatrix conflict-free

// u32-index offsets of the five 128x36 tiles
#define OQH 0
#define OKH (OQH + 128 * STR)
#define OKL (OKH + 128 * STR)
#define OVH (OKL + 128 * STR)
#define OVL (OVH + 128 * STR)
#define SMEM_U32 (OVL + 128 * STR)      // 23040 u32 = 92160 B -> 2 CTAs/SM

// pack two floats -> f16x2 (first arg -> bits[15:0], second -> bits[31:16])
static __device__ __forceinline__ uint32_t packh(float lo, float hi) {
    uint32_t r;
    asm("cvt.rn.f16x2.f32 %0, %1, %2;" : "=r"(r) : "f"(hi), "f"(lo));
    return r;
}
static __device__ __forceinline__ float f16rt(float x) {
    return __half2float(__float2half_rn(x));
}
static __device__ __forceinline__ uint32_t smem_u32(const void* p) {
    uint32_t a;
    asm("{ .reg .u64 t; cvta.to.shared.u64 t, %1; cvt.u32.u64 %0, t; }" : "=r"(a) : "l"(p));
    return a;
}

// D += A * B  (m16n8k16, fp16 in, f32 accum)
static __device__ __forceinline__ void mma16816(float* d, const uint32_t* a,
                                                uint32_t b0, uint32_t b1) {
    asm volatile(
        "mma.sync.aligned.m16n8k16.row.col.f32.f16.f16.f32 "
        "{%0,%1,%2,%3}, {%4,%5,%6,%7}, {%8,%9}, {%0,%1,%2,%3};"
        : "+f"(d[0]), "+f"(d[1]), "+f"(d[2]), "+f"(d[3])
        : "r"(a[0]), "r"(a[1]), "r"(a[2]), "r"(a[3]), "r"(b0), "r"(b1));
}

#define LDSM_X4(r, a) \
    asm volatile("ldmatrix.sync.aligned.m8n8.x4.shared.b16 {%0,%1,%2,%3}, [%4];" \
        : "=r"((r)[0]), "=r"((r)[1]), "=r"((r)[2]), "=r"((r)[3]) : "r"(a))
#define LDSM_X4T(r, a) \
    asm volatile("ldmatrix.sync.aligned.m8n8.x4.trans.shared.b16 {%0,%1,%2,%3}, [%4];" \
        : "=r"((r)[0]), "=r"((r)[1]), "=r"((r)[2]), "=r"((r)[3]) : "r"(a))

// split a float4 into fp16 hi packs and fp16 residual packs
static __device__ __forceinline__ void split4(float4 x, uint2& h, uint2& l) {
    float hx = f16rt(x.x), hy = f16rt(x.y), hz = f16rt(x.z), hw = f16rt(x.w);
    h = make_uint2(packh(hx, hy), packh(hz, hw));
    l = make_uint2(packh(x.x - hx, x.y - hy), packh(x.z - hz, x.w - hw));
}

__global__ __launch_bounds__(256, 2)
void attn_h16_kernel(const float* __restrict__ qg_,
                     const float* __restrict__ kg_,
                     const float* __restrict__ vg_,
                     const float* __restrict__ biasg,
                     float* __restrict__ outg,
                     float* __restrict__ attng)
{
    extern __shared__ uint32_t smu[];

    const int t = threadIdx.x;
    const int b = blockIdx.x;
    const int h = blockIdx.y;

    const size_t base  = (((size_t)h * BSZ + b) * LL) * DD;
    const size_t abase = (((size_t)h * BSZ + b) * LL) * LL;
    const float4* q4 = (const float4*)(qg_ + base);
    const float4* k4 = (const float4*)(kg_ + base);
    const float4* v4 = (const float4*)(vg_ + base);
    const float*  bg = biasg + (size_t)h * LL * LL;
    float*        ag = attng + abase;
    float*        og = outg + base;

    // ---- Stage: Q hi only; K, V hi+lo; row-major, 36-u32 row stride ----
    #pragma unroll
    for (int it = 0; it < 8; ++it) {
        int idx = t + it * 256;               // 0..2047
        int so = (idx >> 4) * STR + 2 * (idx & 15);
        float4 x = q4[idx];
        *(uint2*)&smu[OQH + so] = make_uint2(packh(x.x, x.y), packh(x.z, x.w));
        uint2 hh, ll;
        split4(k4[idx], hh, ll);
        *(uint2*)&smu[OKH + so] = hh; *(uint2*)&smu[OKL + so] = ll;
        split4(v4[idx], hh, ll);
        *(uint2*)&smu[OVH + so] = hh; *(uint2*)&smu[OVL + so] = ll;
    }
    __syncthreads();

    const int w = t >> 5, lane = t & 31;
    const int g = lane >> 2, tq = lane & 3;
    const int i0 = w * 16;
    const int rA = i0 + g, rB = i0 + g + 8;

    // ---- per-lane ldmatrix base addresses (bytes) ----
    const uint32_t sb = smem_u32(smu);
    const int lr = lane & 7, lsel = lane >> 3;
    // A (Qh): m0 rows i0..+7 klo | m1 rows +8 klo | m2 rows i0..7 khi | m3 +8 khi
    const uint32_t aQh = sb + 4u * (OQH + (uint32_t)((i0 + (lsel & 1) * 8 + lr) * STR
                                                     + (lsel >> 1) * 4));
    // B (K): m0 Kh b0 | m1 Kh b1 | m2 Kl b0 | m3 Kl b1
    const uint32_t aKb = sb + 4u * ((lsel >= 2 ? OKL : OKH)
                                    + (uint32_t)(lr * STR + (lsel & 1) * 4));
    // B (V, trans): m0 Vh | m1 Vh +8 rows | m2 Vl | m3 Vl +8
    const uint32_t aVb = sb + 4u * ((lsel >= 2 ? OVL : OVH)
                                    + (uint32_t)(((lsel & 1) * 8 + lr) * STR));

    // =================== MMA 1: S = Qh (Kh + Kl)^T ===================
    float S[16][4];
    #pragma unroll
    for (int nt = 0; nt < 16; ++nt)
        S[nt][0] = S[nt][1] = S[nt][2] = S[nt][3] = 0.f;

    #pragma unroll
    for (int u = 0; u < 4; ++u) {             // k-chunks over d (4 x 16)
        uint32_t qh[4];
        LDSM_X4(qh, aQh + 32u * u);
        #pragma unroll
        for (int nt = 0; nt < 16; ++nt) {
            uint32_t bb[4];
            LDSM_X4(bb, aKb + (uint32_t)(nt * 8 * STR * 4) + 32u * u);
            mma16816(S[nt], qh, bb[0], bb[1]);   // qh*kh
            mma16816(S[nt], qh, bb[2], bb[3]);   // qh*kl
        }
    }

    // =================== softmax (register/warp-local) ===================
    const float* bA = bg + (size_t)rA * LL;
    const float* bB = bg + (size_t)rB * LL;
    float mA = -1e30f, mB = -1e30f;
    #pragma unroll
    for (int nt = 0; nt < 16; ++nt) {
        float2 b0 = __ldg((const float2*)&bA[8 * nt + 2 * tq]);
        float2 b1 = __ldg((const float2*)&bB[8 * nt + 2 * tq]);
        S[nt][0] = fmaf(S[nt][0], 0.125f, b0.x);
        S[nt][1] = fmaf(S[nt][1], 0.125f, b0.y);
        S[nt][2] = fmaf(S[nt][2], 0.125f, b1.x);
        S[nt][3] = fmaf(S[nt][3], 0.125f, b1.y);
        mA = fmaxf(mA, fmaxf(S[nt][0], S[nt][1]));
        mB = fmaxf(mB, fmaxf(S[nt][2], S[nt][3]));
    }
    mA = fmaxf(mA, __shfl_xor_sync(0xffffffffu, mA, 1));
    mA = fmaxf(mA, __shfl_xor_sync(0xffffffffu, mA, 2));
    mB = fmaxf(mB, __shfl_xor_sync(0xffffffffu, mB, 1));
    mB = fmaxf(mB, __shfl_xor_sync(0xffffffffu, mB, 2));

    float sA = 0.f, sB = 0.f;
    #pragma unroll
    for (int nt = 0; nt < 16; ++nt) {
        S[nt][0] = __expf(S[nt][0] - mA); sA += S[nt][0];
        S[nt][1] = __expf(S[nt][1] - mA); sA += S[nt][1];
        S[nt][2] = __expf(S[nt][2] - mB); sB += S[nt][2];
        S[nt][3] = __expf(S[nt][3] - mB); sB += S[nt][3];
    }
    sA += __shfl_xor_sync(0xffffffffu, sA, 1);
    sA += __shfl_xor_sync(0xffffffffu, sA, 2);
    sB += __shfl_xor_sync(0xffffffffu, sB, 1);
    sB += __shfl_xor_sync(0xffffffffu, sB, 2);
    const float iA = 1.f / sA, iB = 1.f / sB;

    float* aA = ag + (size_t)rA * LL;
    float* aB = ag + (size_t)rB * LL;
    #pragma unroll
    for (int nt = 0; nt < 16; ++nt) {
        S[nt][0] *= iA; S[nt][1] *= iA; S[nt][2] *= iB; S[nt][3] *= iB;
        *(float2*)&aA[8 * nt + 2 * tq] = make_float2(S[nt][0], S[nt][1]);
        *(float2*)&aB[8 * nt + 2 * tq] = make_float2(S[nt][2], S[nt][3]);
    }

    // =================== MMA 2: O = Ph (Vh + Vl) ===================
    float O[8][4];
    #pragma unroll
    for (int nt = 0; nt < 8; ++nt)
        O[nt][0] = O[nt][1] = O[nt][2] = O[nt][3] = 0.f;

    #pragma unroll
    for (int u = 0; u < 8; ++u) {             // k-chunks over j (8 x 16)
        uint32_t aH[4];
        aH[0] = packh(S[2 * u][0], S[2 * u][1]);
        aH[1] = packh(S[2 * u][2], S[2 * u][3]);
        aH[2] = packh(S[2 * u + 1][0], S[2 * u + 1][1]);
        aH[3] = packh(S[2 * u + 1][2], S[2 * u + 1][3]);
        #pragma unroll
        for (int nt = 0; nt < 8; ++nt) {
            uint32_t bb[4];
            LDSM_X4T(bb, aVb + (uint32_t)(u * 16 * STR * 4) + (uint32_t)(nt * 16));
            mma16816(O[nt], aH, bb[0], bb[1]);   // ph*vh
            mma16816(O[nt], aH, bb[2], bb[3]);   // ph*vl
        }
    }

    float* oA = og + (size_t)rA * DD;
    float* oB = og + (size_t)rB * DD;
    #pragma unroll
    for (int nt = 0; nt < 8; ++nt) {
        *(float2*)&oA[8 * nt + 2 * tq] = make_float2(O[nt][0], O[nt][1]);
        *(float2*)&oB[8 * nt + 2 * tq] = make_float2(O[nt][2], O[nt][3]);
    }
}

extern "C" void kernel_launch(void* const* d_in, const int* in_sizes, int n_in,
                              void* d_out, int out_size)
{
    const float* q    = (const float*)d_in[0];
    const float* k    = (const float*)d_in[1];
    const float* v    = (const float*)d_in[2];
    const float* bias = (const float*)d_in[3];

    float* out  = (float*)d_out;
    float* attn = out + (size_t)HH * BSZ * LL * DD;

    const size_t smem = (size_t)SMEM_U32 * 4;   // 92160 B
    cudaFuncSetAttribute(attn_h16_kernel,
                         cudaFuncAttributeMaxDynamicSharedMemorySize, (int)smem);

    dim3 grid(BSZ, HH);
    attn_h16_kernel<<<grid, 256, smem>>>(q, k, v, bias, out, attn);
}

// round 8
// speedup vs baseline: 1.5402x; 1.1497x over previous
#include <cuda_runtime.h>
#include <cuda_fp16.h>
#include <cstdint>

// q,k,v: (H=8, B=256, L=128, D=64) fp32 ; pos_bias: (H,1,L,L)
// d_out = [ out (H,B,L,D) | attn (H,B,L,L) ]
// fp16 split on K (2-pass MMA1), plain fp16 V (1-pass MMA2),
// bias preloaded into MMA accumulators.
#define HH 8
#define BSZ 256
#define LL 128
#define DD 64
#define STR 36   // u32 stride per tile row; 36 % 32 == 4 -> ldmatrix conflict-free

// u32-index offsets of the four 128x36 tiles
#define OQH 0
#define OKH (OQH + 128 * STR)
#define OKL (OKH + 128 * STR)
#define OVH (OKL + 128 * STR)
#define SMEM_U32 (OVH + 128 * STR)      // 18432 u32 = 73728 B

static __device__ __forceinline__ uint32_t packh(float lo, float hi) {
    uint32_t r;
    asm("cvt.rn.f16x2.f32 %0, %1, %2;" : "=r"(r) : "f"(hi), "f"(lo));
    return r;
}
static __device__ __forceinline__ float f16rt(float x) {
    return __half2float(__float2half_rn(x));
}
static __device__ __forceinline__ uint32_t smem_u32(const void* p) {
    uint32_t a;
    asm("{ .reg .u64 t; cvta.to.shared.u64 t, %1; cvt.u32.u64 %0, t; }" : "=r"(a) : "l"(p));
    return a;
}
static __device__ __forceinline__ float ex2f(float x) {
    float r;
    asm("ex2.approx.f32 %0, %1;" : "=f"(r) : "f"(x));
    return r;
}

// D += A * B  (m16n8k16, fp16 in, f32 accum)
static __device__ __forceinline__ void mma16816(float* d, const uint32_t* a,
                                                uint32_t b0, uint32_t b1) {
    asm volatile(
        "mma.sync.aligned.m16n8k16.row.col.f32.f16.f16.f32 "
        "{%0,%1,%2,%3}, {%4,%5,%6,%7}, {%8,%9}, {%0,%1,%2,%3};"
        : "+f"(d[0]), "+f"(d[1]), "+f"(d[2]), "+f"(d[3])
        : "r"(a[0]), "r"(a[1]), "r"(a[2]), "r"(a[3]), "r"(b0), "r"(b1));
}

#define LDSM_X4(r, a) \
    asm volatile("ldmatrix.sync.aligned.m8n8.x4.shared.b16 {%0,%1,%2,%3}, [%4];" \
        : "=r"((r)[0]), "=r"((r)[1]), "=r"((r)[2]), "=r"((r)[3]) : "r"(a))
#define LDSM_X2T(r, a) \
    asm volatile("ldmatrix.sync.aligned.m8n8.x2.trans.shared.b16 {%0,%1}, [%2];" \
        : "=r"((r)[0]), "=r"((r)[1]) : "r"(a))

// split a float4 into fp16 hi packs and fp16 residual packs
static __device__ __forceinline__ void split4(float4 x, uint2& h, uint2& l) {
    float hx = f16rt(x.x), hy = f16rt(x.y), hz = f16rt(x.z), hw = f16rt(x.w);
    h = make_uint2(packh(hx, hy), packh(hz, hw));
    l = make_uint2(packh(x.x - hx, x.y - hy), packh(x.z - hz, x.w - hw));
}

__global__ __launch_bounds__(256, 2)
void attn_h16b_kernel(const float* __restrict__ qg_,
                      const float* __restrict__ kg_,
                      const float* __restrict__ vg_,
                      const float* __restrict__ biasg,
                      float* __restrict__ outg,
                      float* __restrict__ attng)
{
    extern __shared__ uint32_t smu[];

    const int t = threadIdx.x;
    const int b = blockIdx.x;
    const int h = blockIdx.y;

    const size_t base  = (((size_t)h * BSZ + b) * LL) * DD;
    const size_t abase = (((size_t)h * BSZ + b) * LL) * LL;
    const float4* q4 = (const float4*)(qg_ + base);
    const float4* k4 = (const float4*)(kg_ + base);
    const float4* v4 = (const float4*)(vg_ + base);
    const float*  bg = biasg + (size_t)h * LL * LL;
    float*        ag = attng + abase;
    float*        og = outg + base;

    const int w = t >> 5, lane = t & 31;
    const int g = lane >> 2, tq = lane & 3;
    const int i0 = w * 16;
    const int rA = i0 + g, rB = i0 + g + 8;

    // ---- Stage: Q hi; K hi+lo; V hi; row-major, 36-u32 row stride ----
    #pragma unroll
    for (int it = 0; it < 8; ++it) {
        int idx = t + it * 256;               // 0..2047
        int so = (idx >> 4) * STR + 2 * (idx & 15);
        float4 x = q4[idx];
        *(uint2*)&smu[OQH + so] = make_uint2(packh(x.x, x.y), packh(x.z, x.w));
        uint2 hh, ll;
        split4(k4[idx], hh, ll);
        *(uint2*)&smu[OKH + so] = hh; *(uint2*)&smu[OKL + so] = ll;
        x = v4[idx];
        *(uint2*)&smu[OVH + so] = make_uint2(packh(x.x, x.y), packh(x.z, x.w));
    }

    // ---- Preload bias into MMA accumulators: S = 8*bias (latency hidden by sync+MMA1) ----
    float S[16][4];
    {
        const float* bA = bg + (size_t)rA * LL;
        const float* bB = bg + (size_t)rB * LL;
        #pragma unroll
        for (int nt = 0; nt < 16; ++nt) {
            float2 b0 = __ldg((const float2*)&bA[8 * nt + 2 * tq]);
            float2 b1 = __ldg((const float2*)&bB[8 * nt + 2 * tq]);
            S[nt][0] = 8.f * b0.x; S[nt][1] = 8.f * b0.y;
            S[nt][2] = 8.f * b1.x; S[nt][3] = 8.f * b1.y;
        }
    }
    __syncthreads();

    // ---- per-lane ldmatrix base addresses (bytes) ----
    const uint32_t sb = smem_u32(smu);
    const int lr = lane & 7, lsel = lane >> 3;
    const uint32_t aQh = sb + 4u * (OQH + (uint32_t)((i0 + (lsel & 1) * 8 + lr) * STR
                                                     + (lsel >> 1) * 4));
    const uint32_t aKb = sb + 4u * ((lsel >= 2 ? OKL : OKH)
                                    + (uint32_t)(lr * STR + (lsel & 1) * 4));
    const uint32_t aVb = sb + 4u * (OVH + (uint32_t)(((lsel & 1) * 8 + lr) * STR));

    // =================== MMA 1: S += Qh (Kh + Kl)^T ===================
    #pragma unroll
    for (int u = 0; u < 4; ++u) {             // k-chunks over d (4 x 16)
        uint32_t qh[4];
        LDSM_X4(qh, aQh + 32u * u);
        #pragma unroll
        for (int nt = 0; nt < 16; ++nt) {
            uint32_t bb[4];
            LDSM_X4(bb, aKb + (uint32_t)(nt * 8 * STR * 4) + 32u * u);
            mma16816(S[nt], qh, bb[0], bb[1]);   // qh*kh
            mma16816(S[nt], qh, bb[2], bb[3]);   // qh*kl
        }
    }

    // =================== softmax (register/warp-local) ===================
    // logits = 0.125 * S ; exp(x) = ex2(x * log2e)
    const float CE = 0.125f * 1.4426950408889634f;
    float mA = -1e30f, mB = -1e30f;
    #pragma unroll
    for (int nt = 0; nt < 16; ++nt) {
        mA = fmaxf(mA, fmaxf(S[nt][0], S[nt][1]));
        mB = fmaxf(mB, fmaxf(S[nt][2], S[nt][3]));
    }
    mA = fmaxf(mA, __shfl_xor_sync(0xffffffffu, mA, 1));
    mA = fmaxf(mA, __shfl_xor_sync(0xffffffffu, mA, 2));
    mB = fmaxf(mB, __shfl_xor_sync(0xffffffffu, mB, 1));
    mB = fmaxf(mB, __shfl_xor_sync(0xffffffffu, mB, 2));
    const float cA = -mA * CE, cB = -mB * CE;

    float sA = 0.f, sB = 0.f;
    #pragma unroll
    for (int nt = 0; nt < 16; ++nt) {
        S[nt][0] = ex2f(fmaf(S[nt][0], CE, cA)); sA += S[nt][0];
        S[nt][1] = ex2f(fmaf(S[nt][1], CE, cA)); sA += S[nt][1];
        S[nt][2] = ex2f(fmaf(S[nt][2], CE, cB)); sB += S[nt][2];
        S[nt][3] = ex2f(fmaf(S[nt][3], CE, cB)); sB += S[nt][3];
    }
    sA += __shfl_xor_sync(0xffffffffu, sA, 1);
    sA += __shfl_xor_sync(0xffffffffu, sA, 2);
    sB += __shfl_xor_sync(0xffffffffu, sB, 1);
    sB += __shfl_xor_sync(0xffffffffu, sB, 2);
    const float iA = 1.f / sA, iB = 1.f / sB;

    float* aA = ag + (size_t)rA * LL;
    float* aB = ag + (size_t)rB * LL;
    #pragma unroll
    for (int nt = 0; nt < 16; ++nt) {
        S[nt][0] *= iA; S[nt][1] *= iA; S[nt][2] *= iB; S[nt][3] *= iB;
        *(float2*)&aA[8 * nt + 2 * tq] = make_float2(S[nt][0], S[nt][1]);
        *(float2*)&aB[8 * nt + 2 * tq] = make_float2(S[nt][2], S[nt][3]);
    }

    // =================== MMA 2: O = Ph Vh ===================
    float O[8][4];
    #pragma unroll
    for (int nt = 0; nt < 8; ++nt)
        O[nt][0] = O[nt][1] = O[nt][2] = O[nt][3] = 0.f;

    #pragma unroll
    for (int u = 0; u < 8; ++u) {             // k-chunks over j (8 x 16)
        uint32_t aH[4];
        aH[0] = packh(S[2 * u][0], S[2 * u][1]);
        aH[1] = packh(S[2 * u][2], S[2 * u][3]);
        aH[2] = packh(S[2 * u + 1][0], S[2 * u + 1][1]);
        aH[3] = packh(S[2 * u + 1][2], S[2 * u + 1][3]);
        #pragma unroll
        for (int nt = 0; nt < 8; ++nt) {
            uint32_t bb[2];
            LDSM_X2T(bb, aVb + (uint32_t)(u * 16 * STR * 4) + (uint32_t)(nt * 16));
            mma16816(O[nt], aH, bb[0], bb[1]);
        }
    }

    float* oA = og + (size_t)rA * DD;
    float* oB = og + (size_t)rB * DD;
    #pragma unroll
    for (int nt = 0; nt < 8; ++nt) {
        *(float2*)&oA[8 * nt + 2 * tq] = make_float2(O[nt][0], O[nt][1]);
        *(float2*)&oB[8 * nt + 2 * tq] = make_float2(O[nt][2], O[nt][3]);
    }
}

extern "C" void kernel_launch(void* const* d_in, const int* in_sizes, int n_in,
                              void* d_out, int out_size)
{
    const float* q    = (const float*)d_in[0];
    const float* k    = (const float*)d_in[1];
    const float* v    = (const float*)d_in[2];
    const float* bias = (const float*)d_in[3];

    float* out  = (float*)d_out;
    float* attn = out + (size_t)HH * BSZ * LL * DD;

    const size_t smem = (size_t)SMEM_U32 * 4;   // 73728 B
    cudaFuncSetAttribute(attn_h16b_kernel,
                         cudaFuncAttributeMaxDynamicSharedMemorySize, (int)smem);

    dim3 grid(BSZ, HH);
    attn_h16b_kernel<<<grid, 256, smem>>>(q, k, v, bias, out, attn);
}

// round 9
// speedup vs baseline: 1.7048x; 1.1068x over previous
#include <cuda_runtime.h>
#include <cuda_fp16.h>
#include <cstdint>

// q,k,v: (H=8, B=256, L=128, D=64) fp32 ; pos_bias: (H,1,L,L)
// d_out = [ out (H,B,L,D) | attn (H,B,L,L) ]
// fp16 split on K (2-pass MMA1), plain fp16 V (1-pass MMA2),
// bias pre-rearranged into fragment order by a prep kernel.
#define HH 8
#define BSZ 256
#define LL 128
#define DD 64
#define STR 36   // u32 stride per tile row; 36 % 32 == 4 -> ldmatrix conflict-free

#define OQH 0
#define OKH (OQH + 128 * STR)
#define OKL (OKH + 128 * STR)
#define OVH (OKL + 128 * STR)
#define SMEM_U32 (OVH + 128 * STR)      // 18432 u32 = 73728 B

// rearranged bias: (h, w, nt, lane) float4 = 8*8*16*32 = 32768 float4 (512 KB)
__device__ float4 g_biasr[HH * 8 * 16 * 32];

static __device__ __forceinline__ uint32_t packh(float lo, float hi) {
    uint32_t r;
    asm("cvt.rn.f16x2.f32 %0, %1, %2;" : "=r"(r) : "f"(hi), "f"(lo));
    return r;
}
static __device__ __forceinline__ float f16rt(float x) {
    return __half2float(__float2half_rn(x));
}
static __device__ __forceinline__ uint32_t smem_u32(const void* p) {
    uint32_t a;
    asm("{ .reg .u64 t; cvta.to.shared.u64 t, %1; cvt.u32.u64 %0, t; }" : "=r"(a) : "l"(p));
    return a;
}
static __device__ __forceinline__ float ex2f(float x) {
    float r;
    asm("ex2.approx.f32 %0, %1;" : "=f"(r) : "f"(x));
    return r;
}

static __device__ __forceinline__ void mma16816(float* d, const uint32_t* a,
                                                uint32_t b0, uint32_t b1) {
    asm volatile(
        "mma.sync.aligned.m16n8k16.row.col.f32.f16.f16.f32 "
        "{%0,%1,%2,%3}, {%4,%5,%6,%7}, {%8,%9}, {%0,%1,%2,%3};"
        : "+f"(d[0]), "+f"(d[1]), "+f"(d[2]), "+f"(d[3])
        : "r"(a[0]), "r"(a[1]), "r"(a[2]), "r"(a[3]), "r"(b0), "r"(b1));
}

#define LDSM_X4(r, a) \
    asm volatile("ldmatrix.sync.aligned.m8n8.x4.shared.b16 {%0,%1,%2,%3}, [%4];" \
        : "=r"((r)[0]), "=r"((r)[1]), "=r"((r)[2]), "=r"((r)[3]) : "r"(a))
#define LDSM_X4T(r, a) \
    asm volatile("ldmatrix.sync.aligned.m8n8.x4.trans.shared.b16 {%0,%1,%2,%3}, [%4];" \
        : "=r"((r)[0]), "=r"((r)[1]), "=r"((r)[2]), "=r"((r)[3]) : "r"(a))

static __device__ __forceinline__ void split4(float4 x, uint2& h, uint2& l) {
    float hx = f16rt(x.x), hy = f16rt(x.y), hz = f16rt(x.z), hw = f16rt(x.w);
    h = make_uint2(packh(hx, hy), packh(hz, hw));
    l = make_uint2(packh(x.x - hx, x.y - hy), packh(x.z - hz, x.w - hw));
}

// ---- prep: 8*bias rearranged into per-(h, warp, nt, lane) fragment order ----
__global__ void bias_prep_kernel(const float* __restrict__ bias)
{
    int tid = blockIdx.x * 256 + threadIdx.x;    // 0..32767
    int lane = tid & 31;
    int nt   = (tid >> 5) & 15;
    int w    = (tid >> 9) & 7;
    int h    = tid >> 12;
    int g = lane >> 2, tq = lane & 3;
    int rA = w * 16 + g, rB = rA + 8, c = 8 * nt + 2 * tq;
    const float* bh = bias + (size_t)h * LL * LL;
    float2 a  = *(const float2*)&bh[rA * LL + c];
    float2 b2 = *(const float2*)&bh[rB * LL + c];
    g_biasr[tid] = make_float4(8.f * a.x, 8.f * a.y, 8.f * b2.x, 8.f * b2.y);
}

__global__ __launch_bounds__(256, 2)
void attn_h16c_kernel(const float* __restrict__ qg_,
                      const float* __restrict__ kg_,
                      const float* __restrict__ vg_,
                      float* __restrict__ outg,
                      float* __restrict__ attng)
{
    extern __shared__ uint32_t smu[];

    const int t = threadIdx.x;
    const int b = blockIdx.x;
    const int h = blockIdx.y;

    const size_t base  = (((size_t)h * BSZ + b) * LL) * DD;
    const size_t abase = (((size_t)h * BSZ + b) * LL) * LL;
    const float4* q4 = (const float4*)(qg_ + base);
    const float4* k4 = (const float4*)(kg_ + base);
    const float4* v4 = (const float4*)(vg_ + base);
    float*        ag = attng + abase;
    float*        og = outg + base;

    const int w = t >> 5, lane = t & 31;
    const int g = lane >> 2, tq = lane & 3;
    const int i0 = w * 16;
    const int rA = i0 + g, rB = i0 + g + 8;

    // ---- Stage: Q hi; K hi+lo; V hi; row-major, 36-u32 row stride ----
    #pragma unroll
    for (int it = 0; it < 8; ++it) {
        int idx = t + it * 256;               // 0..2047
        int so = (idx >> 4) * STR + 2 * (idx & 15);
        float4 x = q4[idx];
        *(uint2*)&smu[OQH + so] = make_uint2(packh(x.x, x.y), packh(x.z, x.w));
        uint2 hh, ll;
        split4(k4[idx], hh, ll);
        *(uint2*)&smu[OKH + so] = hh; *(uint2*)&smu[OKL + so] = ll;
        x = v4[idx];
        *(uint2*)&smu[OVH + so] = make_uint2(packh(x.x, x.y), packh(x.z, x.w));
    }

    // ---- Preload S = 8*bias from the rearranged buffer (fully coalesced) ----
    float S[16][4];
    {
        const float4* br = g_biasr + (((h * 8 + w) * 16) * 32 + lane);
        #pragma unroll
        for (int nt = 0; nt < 16; ++nt) {
            float4 bb = __ldg(&br[nt * 32]);
            S[nt][0] = bb.x; S[nt][1] = bb.y; S[nt][2] = bb.z; S[nt][3] = bb.w;
        }
    }
    __syncthreads();

    // ---- per-lane ldmatrix base addresses (bytes) ----
    const uint32_t sb = smem_u32(smu);
    const int lr = lane & 7, lsel = lane >> 3;
    const uint32_t aQh = sb + 4u * (OQH + (uint32_t)((i0 + (lsel & 1) * 8 + lr) * STR
                                                     + (lsel >> 1) * 4));
    const uint32_t aKb = sb + 4u * ((lsel >= 2 ? OKL : OKH)
                                    + (uint32_t)(lr * STR + (lsel & 1) * 4));
    // V (trans, x4): m0/m1 = rows +0/+8 of col-block nt2*16; m2/m3 same rows, +8 cols
    const uint32_t aVb = sb + 4u * (OVH + (uint32_t)(((lsel & 1) * 8 + lr) * STR))
                         + (uint32_t)((lsel >> 1) * 16);

    // =================== MMA 1: S += Qh (Kh + Kl)^T ===================
    #pragma unroll
    for (int u = 0; u < 4; ++u) {             // k-chunks over d (4 x 16)
        uint32_t qh[4];
        LDSM_X4(qh, aQh + 32u * u);
        #pragma unroll
        for (int nt = 0; nt < 16; ++nt) {
            uint32_t bb[4];
            LDSM_X4(bb, aKb + (uint32_t)(nt * 8 * STR * 4) + 32u * u);
            mma16816(S[nt], qh, bb[0], bb[1]);   // qh*kh
            mma16816(S[nt], qh, bb[2], bb[3]);   // qh*kl
        }
    }

    // =================== softmax (register/warp-local) ===================
    const float CE = 0.125f * 1.4426950408889634f;
    float mA = -1e30f, mB = -1e30f;
    #pragma unroll
    for (int nt = 0; nt < 16; ++nt) {
        mA = fmaxf(mA, fmaxf(S[nt][0], S[nt][1]));
        mB = fmaxf(mB, fmaxf(S[nt][2], S[nt][3]));
    }
    mA = fmaxf(mA, __shfl_xor_sync(0xffffffffu, mA, 1));
    mA = fmaxf(mA, __shfl_xor_sync(0xffffffffu, mA, 2));
    mB = fmaxf(mB, __shfl_xor_sync(0xffffffffu, mB, 1));
    mB = fmaxf(mB, __shfl_xor_sync(0xffffffffu, mB, 2));
    const float cA = -mA * CE, cB = -mB * CE;

    float sA = 0.f, sB = 0.f;
    #pragma unroll
    for (int nt = 0; nt < 16; ++nt) {
        S[nt][0] = ex2f(fmaf(S[nt][0], CE, cA)); sA += S[nt][0];
        S[nt][1] = ex2f(fmaf(S[nt][1], CE, cA)); sA += S[nt][1];
        S[nt][2] = ex2f(fmaf(S[nt][2], CE, cB)); sB += S[nt][2];
        S[nt][3] = ex2f(fmaf(S[nt][3], CE, cB)); sB += S[nt][3];
    }
    sA += __shfl_xor_sync(0xffffffffu, sA, 1);
    sA += __shfl_xor_sync(0xffffffffu, sA, 2);
    sB += __shfl_xor_sync(0xffffffffu, sB, 1);
    sB += __shfl_xor_sync(0xffffffffu, sB, 2);
    const float iA = 1.f / sA, iB = 1.f / sB;

    float* aA = ag + (size_t)rA * LL;
    float* aB = ag + (size_t)rB * LL;
    #pragma unroll
    for (int nt = 0; nt < 16; ++nt) {
        S[nt][0] *= iA; S[nt][1] *= iA; S[nt][2] *= iB; S[nt][3] *= iB;
        *(float2*)&aA[8 * nt + 2 * tq] = make_float2(S[nt][0], S[nt][1]);
        *(float2*)&aB[8 * nt + 2 * tq] = make_float2(S[nt][2], S[nt][3]);
    }

    // =================== MMA 2: O = Ph Vh ===================
    float O[8][4];
    #pragma unroll
    for (int nt = 0; nt < 8; ++nt)
        O[nt][0] = O[nt][1] = O[nt][2] = O[nt][3] = 0.f;

    #pragma unroll
    for (int u = 0; u < 8; ++u) {             // k-chunks over j (8 x 16)
        uint32_t aH[4];
        aH[0] = packh(S[2 * u][0], S[2 * u][1]);
        aH[1] = packh(S[2 * u][2], S[2 * u][3]);
        aH[2] = packh(S[2 * u + 1][0], S[2 * u + 1][1]);
        aH[3] = packh(S[2 * u + 1][2], S[2 * u + 1][3]);
        #pragma unroll
        for (int nt2 = 0; nt2 < 4; ++nt2) {   // two n8-tiles per ldmatrix.x4.trans
            uint32_t bb[4];
            LDSM_X4T(bb, aVb + (uint32_t)(u * 16 * STR * 4) + (uint32_t)(nt2 * 32));
            mma16816(O[2 * nt2],     aH, bb[0], bb[1]);
            mma16816(O[2 * nt2 + 1], aH, bb[2], bb[3]);
        }
    }

    float* oA = og + (size_t)rA * DD;
    float* oB = og + (size_t)rB * DD;
    #pragma unroll
    for (int nt = 0; nt < 8; ++nt) {
        *(float2*)&oA[8 * nt + 2 * tq] = make_float2(O[nt][0], O[nt][1]);
        *(float2*)&oB[8 * nt + 2 * tq] = make_float2(O[nt][2], O[nt][3]);
    }
}

extern "C" void kernel_launch(void* const* d_in, const int* in_sizes, int n_in,
                              void* d_out, int out_size)
{
    const float* q    = (const float*)d_in[0];
    const float* k    = (const float*)d_in[1];
    const float* v    = (const float*)d_in[2];
    const float* bias = (const float*)d_in[3];

    float* out  = (float*)d_out;
    float* attn = out + (size_t)HH * BSZ * LL * DD;

    bias_prep_kernel<<<128, 256>>>(bias);

    const size_t smem = (size_t)SMEM_U32 * 4;   // 73728 B
    cudaFuncSetAttribute(attn_h16c_kernel,
                         cudaFuncAttributeMaxDynamicSharedMemorySize, (int)smem);

    dim3 grid(BSZ, HH);
    attn_h16c_kernel<<<grid, 256, smem>>>(q, k, v, out, attn);
}

// round 10
// speedup vs baseline: 1.9761x; 1.1592x over previous
#include <cuda_runtime.h>
#include <cuda_fp16.h>
#include <cstdint>

// q,k,v: (H=8, B=256, L=128, D=64) fp32 ; pos_bias: (H,1,L,L)
// d_out = [ out (H,B,L,D) | attn (H,B,L,L) ]
// Plain fp16 Q/K/V (rel_err budget ~5e-4 < 1e-3), bias pre-rearranged,
// deferred softmax normalization, streaming stores.
#define HH 8
#define BSZ 256
#define LL 128
#define DD 64
#define STR 36   // u32 stride per tile row; 36 % 32 == 4 -> ldmatrix conflict-free

#define OQH 0
#define OKH (OQH + 128 * STR)
#define OVH (OKH + 128 * STR)
#define SMEM_U32 (OVH + 128 * STR)      // 13824 u32 = 55296 B

// rearranged bias: (h, w, nt, lane) float4 = 8*8*16*32 = 32768 float4 (512 KB)
__device__ float4 g_biasr[HH * 8 * 16 * 32];

static __device__ __forceinline__ uint32_t packh(float lo, float hi) {
    uint32_t r;
    asm("cvt.rn.f16x2.f32 %0, %1, %2;" : "=r"(r) : "f"(hi), "f"(lo));
    return r;
}
static __device__ __forceinline__ uint32_t smem_u32(const void* p) {
    uint32_t a;
    asm("{ .reg .u64 t; cvta.to.shared.u64 t, %1; cvt.u32.u64 %0, t; }" : "=r"(a) : "l"(p));
    return a;
}
static __device__ __forceinline__ float ex2f(float x) {
    float r;
    asm("ex2.approx.f32 %0, %1;" : "=f"(r) : "f"(x));
    return r;
}
static __device__ __forceinline__ void stcs2(float* p, float x, float y) {
    asm volatile("st.global.cs.v2.f32 [%0], {%1,%2};" :: "l"(p), "f"(x), "f"(y) : "memory");
}

static __device__ __forceinline__ void mma16816(float* d, const uint32_t* a,
                                                uint32_t b0, uint32_t b1) {
    asm volatile(
        "mma.sync.aligned.m16n8k16.row.col.f32.f16.f16.f32 "
        "{%0,%1,%2,%3}, {%4,%5,%6,%7}, {%8,%9}, {%0,%1,%2,%3};"
        : "+f"(d[0]), "+f"(d[1]), "+f"(d[2]), "+f"(d[3])
        : "r"(a[0]), "r"(a[1]), "r"(a[2]), "r"(a[3]), "r"(b0), "r"(b1));
}

#define LDSM_X4(r, a) \
    asm volatile("ldmatrix.sync.aligned.m8n8.x4.shared.b16 {%0,%1,%2,%3}, [%4];" \
        : "=r"((r)[0]), "=r"((r)[1]), "=r"((r)[2]), "=r"((r)[3]) : "r"(a))
#define LDSM_X4T(r, a) \
    asm volatile("ldmatrix.sync.aligned.m8n8.x4.trans.shared.b16 {%0,%1,%2,%3}, [%4];" \
        : "=r"((r)[0]), "=r"((r)[1]), "=r"((r)[2]), "=r"((r)[3]) : "r"(a))

// ---- prep: 8*bias rearranged into per-(h, warp, nt, lane) fragment order ----
__global__ void bias_prep_kernel(const float* __restrict__ bias)
{
    int tid = blockIdx.x * 256 + threadIdx.x;    // 0..32767
    int lane = tid & 31;
    int nt   = (tid >> 5) & 15;
    int w    = (tid >> 9) & 7;
    int h    = tid >> 12;
    int g = lane >> 2, tq = lane & 3;
    int rA = w * 16 + g, rB = rA + 8, c = 8 * nt + 2 * tq;
    const float* bh = bias + (size_t)h * LL * LL;
    float2 a  = *(const float2*)&bh[rA * LL + c];
    float2 b2 = *(const float2*)&bh[rB * LL + c];
    g_biasr[tid] = make_float4(8.f * a.x, 8.f * a.y, 8.f * b2.x, 8.f * b2.y);
}

__global__ __launch_bounds__(256, 2)
void attn_h16d_kernel(const float* __restrict__ qg_,
                      const float* __restrict__ kg_,
                      const float* __restrict__ vg_,
                      float* __restrict__ outg,
                      float* __restrict__ attng)
{
    extern __shared__ uint32_t smu[];

    const int t = threadIdx.x;
    const int b = blockIdx.x;
    const int h = blockIdx.y;

    const size_t base  = (((size_t)h * BSZ + b) * LL) * DD;
    const size_t abase = (((size_t)h * BSZ + b) * LL) * LL;
    const float4* q4 = (const float4*)(qg_ + base);
    const float4* k4 = (const float4*)(kg_ + base);
    const float4* v4 = (const float4*)(vg_ + base);
    float*        ag = attng + abase;
    float*        og = outg + base;

    const int w = t >> 5, lane = t & 31;
    const int g = lane >> 2, tq = lane & 3;
    const int i0 = w * 16;
    const int rA = i0 + g, rB = i0 + g + 8;

    // ---- Stage Q, K, V as plain fp16, row-major, 36-u32 row stride ----
    #pragma unroll
    for (int it = 0; it < 8; ++it) {
        int idx = t + it * 256;               // 0..2047
        int so = (idx >> 4) * STR + 2 * (idx & 15);
        float4 x = q4[idx];
        *(uint2*)&smu[OQH + so] = make_uint2(packh(x.x, x.y), packh(x.z, x.w));
        x = k4[idx];
        *(uint2*)&smu[OKH + so] = make_uint2(packh(x.x, x.y), packh(x.z, x.w));
        x = v4[idx];
        *(uint2*)&smu[OVH + so] = make_uint2(packh(x.x, x.y), packh(x.z, x.w));
    }

    // ---- Preload S = 8*bias from the rearranged buffer (fully coalesced) ----
    float S[16][4];
    {
        const float4* br = g_biasr + (((h * 8 + w) * 16) * 32 + lane);
        #pragma unroll
        for (int nt = 0; nt < 16; ++nt) {
            float4 bb = __ldg(&br[nt * 32]);
            S[nt][0] = bb.x; S[nt][1] = bb.y; S[nt][2] = bb.z; S[nt][3] = bb.w;
        }
    }
    __syncthreads();

    // ---- per-lane ldmatrix base addresses (bytes) ----
    const uint32_t sb = smem_u32(smu);
    const int lr = lane & 7;
    const int lsel = lane >> 3;               // 0..3
    // A (Q): m0/m1 = rows i0..+7 / +8..15 at k-lo, m2/m3 same at k-hi
    const uint32_t aQh = sb + 4u * (OQH + (uint32_t)((i0 + (lsel & 1) * 8 + lr) * STR
                                                     + (lsel >> 1) * 4));
    // B (K, paired nt): m0/m1 = rows ntp16..+8 (b0,b1), m2/m3 = rows +8..16 (b0,b1)
    const uint32_t aKb = sb + 4u * (OKH + (uint32_t)(((lane >> 4) * 8 + lr) * STR
                                                     + (lsel & 1) * 4));
    // B (V, trans x4): m0/m1 = j rows +0/+8 of d-block, m2/m3 same rows, +8 d
    const uint32_t aVb = sb + 4u * (OVH + (uint32_t)(((lsel & 1) * 8 + lr) * STR))
                         + (uint32_t)((lsel >> 1) * 16);

    // =================== MMA 1: S += Qh Kh^T (single pass) ===================
    #pragma unroll
    for (int u = 0; u < 4; ++u) {             // k-chunks over d (4 x 16)
        uint32_t qh[4];
        LDSM_X4(qh, aQh + 32u * u);
        #pragma unroll
        for (int ntp = 0; ntp < 8; ++ntp) {   // 2 n-tiles per ldmatrix.x4
            uint32_t bb[4];
            LDSM_X4(bb, aKb + (uint32_t)(ntp * 16 * STR * 4) + 32u * u);
            mma16816(S[2 * ntp],     qh, bb[0], bb[1]);
            mma16816(S[2 * ntp + 1], qh, bb[2], bb[3]);
        }
    }

    // =================== softmax: max + exp (normalization deferred) ===================
    const float CE = 0.125f * 1.4426950408889634f;
    float mA = -1e30f, mB = -1e30f;
    #pragma unroll
    for (int nt = 0; nt < 16; ++nt) {
        mA = fmaxf(mA, fmaxf(S[nt][0], S[nt][1]));
        mB = fmaxf(mB, fmaxf(S[nt][2], S[nt][3]));
    }
    mA = fmaxf(mA, __shfl_xor_sync(0xffffffffu, mA, 1));
    mA = fmaxf(mA, __shfl_xor_sync(0xffffffffu, mA, 2));
    mB = fmaxf(mB, __shfl_xor_sync(0xffffffffu, mB, 1));
    mB = fmaxf(mB, __shfl_xor_sync(0xffffffffu, mB, 2));
    const float cA = -mA * CE, cB = -mB * CE;

    float sA = 0.f, sB = 0.f;
    #pragma unroll
    for (int nt = 0; nt < 16; ++nt) {
        S[nt][0] = ex2f(fmaf(S[nt][0], CE, cA)); sA += S[nt][0];
        S[nt][1] = ex2f(fmaf(S[nt][1], CE, cA)); sA += S[nt][1];
        S[nt][2] = ex2f(fmaf(S[nt][2], CE, cB)); sB += S[nt][2];
        S[nt][3] = ex2f(fmaf(S[nt][3], CE, cB)); sB += S[nt][3];
    }

    // =================== MMA 2: O = E Vh (unnormalized) ===================
    float O[8][4];
    #pragma unroll
    for (int nt = 0; nt < 8; ++nt)
        O[nt][0] = O[nt][1] = O[nt][2] = O[nt][3] = 0.f;

    #pragma unroll
    for (int u = 0; u < 8; ++u) {             // k-chunks over j (8 x 16)
        uint32_t aH[4];
        aH[0] = packh(S[2 * u][0], S[2 * u][1]);
        aH[1] = packh(S[2 * u][2], S[2 * u][3]);
        aH[2] = packh(S[2 * u + 1][0], S[2 * u + 1][1]);
        aH[3] = packh(S[2 * u + 1][2], S[2 * u + 1][3]);
        #pragma unroll
        for (int nt2 = 0; nt2 < 4; ++nt2) {   // two n8-tiles per ldmatrix.x4.trans
            uint32_t bb[4];
            LDSM_X4T(bb, aVb + (uint32_t)(u * 16 * STR * 4) + (uint32_t)(nt2 * 32));
            mma16816(O[2 * nt2],     aH, bb[0], bb[1]);
            mma16816(O[2 * nt2 + 1], aH, bb[2], bb[3]);
        }
    }

    // ---- finish the sum reduction (overlapped with MMA2 by the scheduler) ----
    sA += __shfl_xor_sync(0xffffffffu, sA, 1);
    sA += __shfl_xor_sync(0xffffffffu, sA, 2);
    sB += __shfl_xor_sync(0xffffffffu, sB, 1);
    sB += __shfl_xor_sync(0xffffffffu, sB, 2);
    const float iA = 1.f / sA, iB = 1.f / sB;

    // ---- attn = E * inv (streaming stores) ----
    {
        float* aA = ag + (size_t)rA * LL;
        float* aB = ag + (size_t)rB * LL;
        #pragma unroll
        for (int nt = 0; nt < 16; ++nt) {
            stcs2(&aA[8 * nt + 2 * tq], S[nt][0] * iA, S[nt][1] * iA);
            stcs2(&aB[8 * nt + 2 * tq], S[nt][2] * iB, S[nt][3] * iB);
        }
    }

    // ---- out = O * inv (streaming stores) ----
    {
        float* oA = og + (size_t)rA * DD;
        float* oB = og + (size_t)rB * DD;
        #pragma unroll
        for (int nt = 0; nt < 8; ++nt) {
            stcs2(&oA[8 * nt + 2 * tq], O[nt][0] * iA, O[nt][1] * iA);
            stcs2(&oB[8 * nt + 2 * tq], O[nt][2] * iB, O[nt][3] * iB);
        }
    }
}

extern "C" void kernel_launch(void* const* d_in, const int* in_sizes, int n_in,
                              void* d_out, int out_size)
{
    const float* q    = (const float*)d_in[0];
    const float* k    = (const float*)d_in[1];
    const float* v    = (const float*)d_in[2];
    const float* bias = (const float*)d_in[3];

    float* out  = (float*)d_out;
    float* attn = out + (size_t)HH * BSZ * LL * DD;

    bias_prep_kernel<<<128, 256>>>(bias);

    const size_t smem = (size_t)SMEM_U32 * 4;   // 55296 B
    cudaFuncSetAttribute(attn_h16d_kernel,
                         cudaFuncAttributeMaxDynamicSharedMemorySize, (int)smem);

    dim3 grid(BSZ, HH);
    attn_h16d_kernel<<<grid, 256, smem>>>(q, k, v, out, attn);
}